// round 1
// baseline (speedup 1.0000x reference)
#include <cuda_runtime.h>

#define BB 2
#define SS 2048
#define DD 1024
#define HH 16
#define DHH 64
#define BHH (BB*HH)
#define MM (BB*SS)

// ---------------- scratch (device-global, no runtime allocation) ----------------
__device__ float g_Qu[(size_t)BHH * SS * DHH];   // (q + u_bias) head-major
__device__ float g_Qv[(size_t)BHH * SS * DHH];   // (q + v_bias) head-major
__device__ float g_Kh[(size_t)BHH * SS * DHH];
__device__ float g_Vh[(size_t)BHH * SS * DHH];
__device__ float g_Ph[(size_t)BHH * SS * DHH];
__device__ float g_S1[(size_t)BHH * SS * SS];    // raw pos scores (pre-shift)
__device__ float g_S2[(size_t)BHH * SS * SS];    // score -> attn (in place)
__device__ float g_O [(size_t)MM * DD];          // attention output, [B*S, D]

// ---------------- 64x64 fp32 GEMM cores (16x16 threads, 4x4 per thread) ----------------
// NT: C[m][n] = sum_k A[m][k] * B[n][k]   (both K-major)
__device__ __forceinline__ void gemm_nt64(const float* __restrict__ A, int lda,
                                          const float* __restrict__ Bm, int ldb,
                                          int K, float acc[4][4])
{
    __shared__ float As[16][64];
    __shared__ float Bs[16][64];
    const int tx = threadIdx.x, ty = threadIdx.y;
    const int tid  = ty * 16 + tx;
    const int lrow = tid >> 2;          // 0..63
    const int lk4  = (tid & 3) << 2;    // 0,4,8,12
    for (int k0 = 0; k0 < K; k0 += 16) {
        float4 a = *(const float4*)(A  + (size_t)lrow * lda + k0 + lk4);
        float4 b = *(const float4*)(Bm + (size_t)lrow * ldb + k0 + lk4);
        As[lk4 + 0][lrow] = a.x; As[lk4 + 1][lrow] = a.y;
        As[lk4 + 2][lrow] = a.z; As[lk4 + 3][lrow] = a.w;
        Bs[lk4 + 0][lrow] = b.x; Bs[lk4 + 1][lrow] = b.y;
        Bs[lk4 + 2][lrow] = b.z; Bs[lk4 + 3][lrow] = b.w;
        __syncthreads();
#pragma unroll
        for (int kk = 0; kk < 16; kk++) {
            float4 a4 = *(const float4*)(&As[kk][ty << 2]);
            float4 b4 = *(const float4*)(&Bs[kk][tx << 2]);
            float av[4] = {a4.x, a4.y, a4.z, a4.w};
            float bv[4] = {b4.x, b4.y, b4.z, b4.w};
#pragma unroll
            for (int i = 0; i < 4; i++)
#pragma unroll
                for (int j = 0; j < 4; j++)
                    acc[i][j] += av[i] * bv[j];
        }
        __syncthreads();
    }
}

// NN: C[m][n] = sum_k A[m][k] * B[k][n]   (A K-major, B N-major; ldb == 64 tile width)
__device__ __forceinline__ void gemm_nn64(const float* __restrict__ A, int lda,
                                          const float* __restrict__ Bm, int ldb,
                                          int K, float acc[4][4])
{
    __shared__ float As[16][64];
    __shared__ float Bs[16][64];
    const int tx = threadIdx.x, ty = threadIdx.y;
    const int tid  = ty * 16 + tx;
    const int lrow = tid >> 2;
    const int lk4  = (tid & 3) << 2;
    const int brow = tid >> 4;          // 0..15
    const int bcol = (tid & 15) << 2;   // 0..60
    for (int k0 = 0; k0 < K; k0 += 16) {
        float4 a = *(const float4*)(A + (size_t)lrow * lda + k0 + lk4);
        As[lk4 + 0][lrow] = a.x; As[lk4 + 1][lrow] = a.y;
        As[lk4 + 2][lrow] = a.z; As[lk4 + 3][lrow] = a.w;
        float4 b = *(const float4*)(Bm + (size_t)(k0 + brow) * ldb + bcol);
        *(float4*)(&Bs[brow][bcol]) = b;
        __syncthreads();
#pragma unroll
        for (int kk = 0; kk < 16; kk++) {
            float4 a4 = *(const float4*)(&As[kk][ty << 2]);
            float4 b4 = *(const float4*)(&Bs[kk][tx << 2]);
            float av[4] = {a4.x, a4.y, a4.z, a4.w};
            float bv[4] = {b4.x, b4.y, b4.z, b4.w};
#pragma unroll
            for (int i = 0; i < 4; i++)
#pragma unroll
                for (int j = 0; j < 4; j++)
                    acc[i][j] += av[i] * bv[j];
        }
        __syncthreads();
    }
}

// ---------------- stage 1: projections  C = A @ W^T (+bias) -> head layout ----------------
// mode 0: Q  -> g_Qu (+bq+u_bias), g_Qv (+bq+v_bias)
// mode 1: K  -> g_Kh (+bk)
// mode 2: V  -> g_Vh (+bv)
// mode 3: P  -> g_Ph (no bias)
__global__ __launch_bounds__(256) void proj_kernel(
    const float* __restrict__ A, const float* __restrict__ W,
    const float* __restrict__ bias,
    const float* __restrict__ e1, const float* __restrict__ e2, int mode)
{
    float acc[4][4] = {};
    const int n0 = blockIdx.x * 64;
    const int m0 = blockIdx.y * 64;
    gemm_nt64(A + (size_t)m0 * DD, DD, W + (size_t)n0 * DD, DD, DD, acc);

    float* out1; float* out2 = nullptr;
    switch (mode) {
        case 0: out1 = g_Qu; out2 = g_Qv; break;
        case 1: out1 = g_Kh; break;
        case 2: out1 = g_Vh; break;
        default: out1 = g_Ph; break;
    }
    const int tx = threadIdx.x, ty = threadIdx.y;
#pragma unroll
    for (int i = 0; i < 4; i++) {
#pragma unroll
        for (int j = 0; j < 4; j++) {
            int m = m0 + ty * 4 + i;
            int n = n0 + tx * 4 + j;
            int b = m >> 11;            // /S
            int s = m & (SS - 1);
            int h = n >> 6;             // /DH
            int d = n & (DHH - 1);
            size_t o = (((size_t)(b * HH + h)) * SS + s) * DHH + d;
            float val = acc[i][j] + (bias ? bias[n] : 0.0f);
            out1[o] = val + (e1 ? e1[n] : 0.0f);
            if (out2) out2[o] = val + e2[n];
        }
    }
}

// ---------------- stage 2a: raw pos scores  S1[q][k] = Qv . Ph ----------------
__global__ __launch_bounds__(256) void pos_score_kernel()
{
    float acc[4][4] = {};
    const int bh = blockIdx.z;
    const int k0 = blockIdx.x * 64;
    const int q0 = blockIdx.y * 64;
    const float* A  = g_Qv + ((size_t)bh * SS + q0) * DHH;
    const float* Bm = g_Ph + ((size_t)bh * SS + k0) * DHH;
    gemm_nt64(A, DHH, Bm, DHH, DHH, acc);
    const int tx = threadIdx.x, ty = threadIdx.y;
#pragma unroll
    for (int i = 0; i < 4; i++)
#pragma unroll
        for (int j = 0; j < 4; j++)
            g_S1[((size_t)bh * SS + (q0 + ty * 4 + i)) * SS + (k0 + tx * 4 + j)] = acc[i][j];
}

// ---------------- stage 2b: content scores + rel_shift(pos) + scale ----------------
// shift(P)[q,k]: k<=q -> P[q, S-1-q+k]; k==q+1 -> 0; k>q+1 -> P[q+1, k-q-2]
__global__ __launch_bounds__(256) void content_score_kernel()
{
    float acc[4][4] = {};
    const int bh = blockIdx.z;
    const int k0 = blockIdx.x * 64;
    const int q0 = blockIdx.y * 64;
    const float* A  = g_Qu + ((size_t)bh * SS + q0) * DHH;
    const float* Bm = g_Kh + ((size_t)bh * SS + k0) * DHH;
    gemm_nt64(A, DHH, Bm, DHH, DHH, acc);
    const int tx = threadIdx.x, ty = threadIdx.y;
    const float scale = 0.03125f;   // 1/sqrt(1024)
#pragma unroll
    for (int i = 0; i < 4; i++) {
#pragma unroll
        for (int j = 0; j < 4; j++) {
            int qg = q0 + ty * 4 + i;
            int kg = k0 + tx * 4 + j;
            float pv;
            if (kg <= qg)
                pv = g_S1[((size_t)bh * SS + qg) * SS + (SS - 1 - qg + kg)];
            else if (kg == qg + 1)
                pv = 0.0f;
            else
                pv = g_S1[((size_t)bh * SS + qg + 1) * SS + (kg - qg - 2)];
            g_S2[((size_t)bh * SS + qg) * SS + kg] = (acc[i][j] + pv) * scale;
        }
    }
}

// ---------------- stage 3: row softmax (in place on g_S2) ----------------
__global__ __launch_bounds__(256) void softmax_kernel()
{
    const size_t row = blockIdx.x;
    float* p = g_S2 + row * SS;
    const int t = threadIdx.x;
    float v[8];
    float m = -1e30f;
#pragma unroll
    for (int i = 0; i < 8; i++) { v[i] = p[t + i * 256]; m = fmaxf(m, v[i]); }
    __shared__ float red[256];
    red[t] = m; __syncthreads();
    for (int s = 128; s > 0; s >>= 1) {
        if (t < s) red[t] = fmaxf(red[t], red[t + s]);
        __syncthreads();
    }
    m = red[0]; __syncthreads();
    float sum = 0.0f;
#pragma unroll
    for (int i = 0; i < 8; i++) { v[i] = __expf(v[i] - m); sum += v[i]; }
    red[t] = sum; __syncthreads();
    for (int s = 128; s > 0; s >>= 1) {
        if (t < s) red[t] += red[t + s];
        __syncthreads();
    }
    float inv = 1.0f / red[0];
#pragma unroll
    for (int i = 0; i < 8; i++) p[t + i * 256] = v[i] * inv;
}

// ---------------- stage 4: attn @ V  -> g_O [B*S, D] ----------------
__global__ __launch_bounds__(256) void attn_v_kernel()
{
    float acc[4][4] = {};
    const int bh = blockIdx.y;
    const int q0 = blockIdx.x * 64;
    const float* A  = g_S2 + ((size_t)bh * SS + q0) * SS;
    const float* Bm = g_Vh + (size_t)bh * SS * DHH;
    gemm_nn64(A, SS, Bm, DHH, SS, acc);
    const int b = bh >> 4;      // /H
    const int h = bh & (HH - 1);
    const int tx = threadIdx.x, ty = threadIdx.y;
#pragma unroll
    for (int i = 0; i < 4; i++)
#pragma unroll
        for (int j = 0; j < 4; j++) {
            int qg = q0 + ty * 4 + i;
            int d  = tx * 4 + j;
            g_O[((size_t)b * SS + qg) * DD + h * DHH + d] = acc[i][j];
        }
}

// ---------------- stage 5: output projection -> d_out ----------------
__global__ __launch_bounds__(256) void out_proj_kernel(
    const float* __restrict__ Wo, const float* __restrict__ bo, float* __restrict__ out)
{
    float acc[4][4] = {};
    const int n0 = blockIdx.x * 64;
    const int m0 = blockIdx.y * 64;
    gemm_nt64(g_O + (size_t)m0 * DD, DD, Wo + (size_t)n0 * DD, DD, DD, acc);
    const int tx = threadIdx.x, ty = threadIdx.y;
#pragma unroll
    for (int i = 0; i < 4; i++)
#pragma unroll
        for (int j = 0; j < 4; j++) {
            int m = m0 + ty * 4 + i;
            int n = n0 + tx * 4 + j;
            out[(size_t)m * DD + n] = acc[i][j] + bo[n];
        }
}

// ---------------- launch ----------------
extern "C" void kernel_launch(void* const* d_in, const int* in_sizes, int n_in,
                              void* d_out, int out_size)
{
    const float* q  = (const float*)d_in[0];
    const float* k  = (const float*)d_in[1];
    const float* v  = (const float*)d_in[2];
    const float* pe = (const float*)d_in[3];
    const float* Wq = (const float*)d_in[4];
    const float* bq = (const float*)d_in[5];
    const float* Wk = (const float*)d_in[6];
    const float* bk = (const float*)d_in[7];
    const float* Wv = (const float*)d_in[8];
    const float* bv = (const float*)d_in[9];
    const float* Wp = (const float*)d_in[10];
    const float* ub = (const float*)d_in[11];
    const float* vb = (const float*)d_in[12];
    const float* Wo = (const float*)d_in[13];
    const float* bo = (const float*)d_in[14];
    float* out = (float*)d_out;

    dim3 blk(16, 16);
    dim3 gproj(DD / 64, MM / 64);           // 16 x 64
    proj_kernel<<<gproj, blk>>>(q,  Wq, bq, ub, vb, 0);
    proj_kernel<<<gproj, blk>>>(k,  Wk, bk, nullptr, nullptr, 1);
    proj_kernel<<<gproj, blk>>>(v,  Wv, bv, nullptr, nullptr, 2);
    proj_kernel<<<gproj, blk>>>(pe, Wp, nullptr, nullptr, nullptr, 3);

    dim3 gsc(SS / 64, SS / 64, BHH);        // 32 x 32 x 32
    pos_score_kernel<<<gsc, blk>>>();
    content_score_kernel<<<gsc, blk>>>();

    softmax_kernel<<<BHH * SS, 256>>>();

    attn_v_kernel<<<dim3(SS / 64, BHH), blk>>>();

    out_proj_kernel<<<dim3(DD / 64, MM / 64), blk>>>(Wo, bo, out);
}

// round 5
// speedup vs baseline: 1.9888x; 1.9888x over previous
#include <cuda_runtime.h>
#include <cstdint>

#define BB 2
#define SS 2048
#define DD 1024
#define HH 16
#define DHH 64
#define BHH 32
#define MM 4096

// ---------------- scratch ----------------
__device__ float g_Qu[(size_t)BHH * SS * DHH];
__device__ float g_Qv[(size_t)BHH * SS * DHH];
__device__ float g_Kh[(size_t)BHH * SS * DHH];
__device__ float g_Vh[(size_t)BHH * SS * DHH];
__device__ float g_VhT[(size_t)BHH * SS * DHH];   // [bh][d][s]
__device__ float g_Ph[(size_t)BHH * SS * DHH];
__device__ float g_S1[(size_t)BHH * SS * SS];     // raw pos scores
__device__ float g_S2[(size_t)BHH * SS * SS];     // score -> attn (in place)
__device__ float g_O [(size_t)MM * DD];

// ---------------- mma.sync tf32 helpers ----------------
__device__ __forceinline__ uint32_t f2tf32(float f) {
    uint32_t t;
    asm("cvt.rna.tf32.f32 %0, %1;" : "=r"(t) : "f"(f));
    return t;
}
__device__ __forceinline__ void mma_tf32(float c[4], const uint32_t a[4], const uint32_t b[2]) {
    asm volatile(
        "mma.sync.aligned.m16n8k8.row.col.f32.tf32.tf32.f32 "
        "{%0,%1,%2,%3}, {%4,%5,%6,%7}, {%8,%9}, {%0,%1,%2,%3};"
        : "+f"(c[0]), "+f"(c[1]), "+f"(c[2]), "+f"(c[3])
        : "r"(a[0]), "r"(a[1]), "r"(a[2]), "r"(a[3]), "r"(b[0]), "r"(b[1]));
}

// ================= tf32 GEMM core =================
// C[128 x NT] = A[128,K] . B[NT,K]^T, block = 256 threads (8 warps).
// BK = 32 (4 k-steps of 8). Smem tiles in fragment-native layout:
//   A: [kstep(4)][mgroup(8)][lane(32)][reg(4)] u32   (16 KB / stage)
//   B: [kstep(4)][ngroup(NT/8)][lane(32)][reg(2)] u32
// Result staged into smem as float [128][NT+4]  (stride mult of 4 -> 16B-aligned float4 rows).

// ---- global -> regs ----
__device__ __forceinline__ void loadA(const float* __restrict__ src, int lda,
                                      int kc, int tid, float4* pa) {
#pragma unroll
    for (int j = 0; j < 4; ++j) {
        int i = tid + j * 256;
        int r = i >> 3, c4 = i & 7;
        pa[j] = *(const float4*)(src + (size_t)r * lda + kc + c4 * 4);
    }
}
template<int NB>
__device__ __forceinline__ void loadB(const float* __restrict__ src, int ldb,
                                      int kc, int tid, float4* pb) {
#pragma unroll
    for (int j = 0; j < NB; ++j) {
        int i = tid + j * 256;
        int r = i >> 3, c4 = i & 7;
        pb[j] = *(const float4*)(src + (size_t)r * ldb + kc + c4 * 4);
    }
}
// ---- regs -> smem (fragment layout, with tf32 convert) ----
__device__ __forceinline__ void storeA(const float4* pa, uint32_t* dst, int tid) {
#pragma unroll
    for (int j = 0; j < 4; ++j) {
        int i = tid + j * 256;
        int r = i >> 3, c4 = i & 7;
        int kstep = c4 >> 1;
        int regb  = ((r >> 3) & 1) + (c4 & 1) * 2;
        int mg    = r >> 4;
        int laneb = (r & 7) * 4;
        const float v[4] = {pa[j].x, pa[j].y, pa[j].z, pa[j].w};
#pragma unroll
        for (int e = 0; e < 4; ++e)
            dst[(((kstep * 8 + mg) * 32) + laneb + e) * 4 + regb] = f2tf32(v[e]);
    }
}
template<int NT, int NB>
__device__ __forceinline__ void storeB(const float4* pb, uint32_t* dst, int tid) {
#pragma unroll
    for (int j = 0; j < NB; ++j) {
        int i = tid + j * 256;
        int r = i >> 3, c4 = i & 7;
        int kstep = c4 >> 1;
        int reg   = c4 & 1;
        int ng    = r >> 3;
        int laneb = (r & 7) * 4;
        const float v[4] = {pb[j].x, pb[j].y, pb[j].z, pb[j].w};
#pragma unroll
        for (int e = 0; e < 4; ++e)
            dst[((kstep * (NT / 8) + ng) * 32 + laneb + e) * 2 + reg] = f2tf32(v[e]);
    }
}

template<int NT>
__device__ void run_gemm(const float* __restrict__ A, int lda,
                         const float* __restrict__ B, int ldb,
                         int K, char* sm) {
    constexpr int NB   = NT / 32;      // B float4 loads per thread
    constexpr int NG   = NT / 8;       // B ngroups
    constexpr int NWN  = NT / 64;      // warps along N
    constexpr int NWM  = 8 / NWN;      // warps along M
    constexpr int MF   = 8 / NWM;      // m16 frags per warp (128 rows / 16 / NWM)
    constexpr int AW   = 4096;         // A stage words
    constexpr int BW   = NT * 32;      // B stage words
    constexpr int STW  = AW + BW;
    constexpr int PAD  = NT + 4;       // staging stride (floats)

    const int tid  = threadIdx.x;
    const int wid  = tid >> 5;
    const int lane = tid & 31;
    const int wm   = wid % NWM;
    const int wn   = wid / NWM;
    const int mgb  = wm * MF;
    const int ngb  = wn * 8;

    uint32_t* s = (uint32_t*)sm;
    float acc[MF][8][4];
#pragma unroll
    for (int i = 0; i < MF; ++i)
#pragma unroll
        for (int j = 0; j < 8; ++j)
#pragma unroll
            for (int e = 0; e < 4; ++e) acc[i][j][e] = 0.0f;

    const int nch = K >> 5;
    {
        float4 pa[4], pb[NB];
        loadA(A, lda, 0, tid, pa);
        loadB<NB>(B, ldb, 0, tid, pb);
        storeA(pa, s, tid);
        storeB<NT, NB>(pb, s + AW, tid);
    }
    __syncthreads();

    for (int c = 0; c < nch; ++c) {
        float4 pa[4], pb[NB];
        const bool more = (c + 1 < nch);
        if (more) {
            loadA(A, lda, (c + 1) * 32, tid, pa);
            loadB<NB>(B, ldb, (c + 1) * 32, tid, pb);
        }
        uint32_t* As = s + (c & 1) * STW;
        uint32_t* Bs = As + AW;
#pragma unroll
        for (int ks = 0; ks < 4; ++ks) {
            uint32_t af[MF][4];
#pragma unroll
            for (int mf = 0; mf < MF; ++mf)
                *(uint4*)af[mf] = *(const uint4*)&As[((ks * 8 + mgb + mf) * 32 + lane) * 4];
            uint32_t bf[8][2];
#pragma unroll
            for (int nf = 0; nf < 8; ++nf)
                *(uint2*)bf[nf] = *(const uint2*)&Bs[((ks * NG + ngb + nf) * 32 + lane) * 2];
#pragma unroll
            for (int mf = 0; mf < MF; ++mf)
#pragma unroll
                for (int nf = 0; nf < 8; ++nf)
                    mma_tf32(acc[mf][nf], af[mf], bf[nf]);
        }
        if (more) {
            uint32_t* d = s + ((c + 1) & 1) * STW;
            storeA(pa, d, tid);
            storeB<NT, NB>(pb, d + AW, tid);
        }
        __syncthreads();
    }

    // stage accumulators -> smem float [128][PAD]
    float* smf = (float*)sm;
    const int gr = lane >> 2, gc = (lane & 3) * 2;
    const int rowb = wm * (MF * 16);
    const int colb = wn * 64;
#pragma unroll
    for (int mf = 0; mf < MF; ++mf) {
#pragma unroll
        for (int nf = 0; nf < 8; ++nf) {
            int row = rowb + mf * 16 + gr;
            int col = colb + nf * 8 + gc;
            smf[row * PAD + col]           = acc[mf][nf][0];
            smf[row * PAD + col + 1]       = acc[mf][nf][1];
            smf[(row + 8) * PAD + col]     = acc[mf][nf][2];
            smf[(row + 8) * PAD + col + 1] = acc[mf][nf][3];
        }
    }
    __syncthreads();
}

// ---------------- stage 1: projections ----------------
__global__ __launch_bounds__(256) void k_proj(
    const float* __restrict__ A, const float* __restrict__ W,
    const float* __restrict__ bias,
    const float* __restrict__ e1, const float* __restrict__ e2, int mode)
{
    extern __shared__ char sm[];
    const int n0 = blockIdx.x * 128, m0 = blockIdx.y * 128;
    run_gemm<128>(A + (size_t)m0 * DD, DD, W + (size_t)n0 * DD, DD, DD, sm);
    float* smf = (float*)sm;
    const int tid = threadIdx.x, wid = tid >> 5, lid = tid & 31;
    const int col4 = lid * 4;
    const int n = n0 + col4;
    const int h = n >> 6;
    const int d = n & 63;
    float4 bb = bias ? *(const float4*)(bias + n) : make_float4(0, 0, 0, 0);
    float4 uu = e1 ? *(const float4*)(e1 + n) : make_float4(0, 0, 0, 0);
    float4 vv = e2 ? *(const float4*)(e2 + n) : make_float4(0, 0, 0, 0);
#pragma unroll
    for (int it = 0; it < 16; ++it) {
        int r = wid * 16 + it;
        float4 v = *(float4*)(smf + r * 132 + col4);
        v.x += bb.x; v.y += bb.y; v.z += bb.z; v.w += bb.w;
        int m = m0 + r, b = m >> 11, ss = m & (SS - 1);
        size_t o = (((size_t)(b * HH + h)) * SS + ss) * DHH + d;
        if (mode == 0) {
            *(float4*)(g_Qu + o) = make_float4(v.x + uu.x, v.y + uu.y, v.z + uu.z, v.w + uu.w);
            *(float4*)(g_Qv + o) = make_float4(v.x + vv.x, v.y + vv.y, v.z + vv.z, v.w + vv.w);
        } else if (mode == 1) *(float4*)(g_Kh + o) = v;
        else if (mode == 2)   *(float4*)(g_Vh + o) = v;
        else                  *(float4*)(g_Ph + o) = v;
    }
}

// ---------------- V transpose: [bh][s][d] -> [bh][d][s] ----------------
__global__ void k_transpose() {
    __shared__ float t[32][33];
    const int bh = blockIdx.z, s0 = blockIdx.x * 32, d0 = blockIdx.y * 32;
    const int tx = threadIdx.x, ty = threadIdx.y;
    for (int i = 0; i < 32; i += 8)
        t[ty + i][tx] = g_Vh[((size_t)bh * SS + s0 + ty + i) * DHH + d0 + tx];
    __syncthreads();
    for (int i = 0; i < 32; i += 8)
        g_VhT[((size_t)bh * DHH + d0 + ty + i) * SS + s0 + tx] = t[tx][ty + i];
}

// ---------------- stage 2a: pos scores ----------------
__global__ __launch_bounds__(256) void k_pos() {
    extern __shared__ char sm[];
    const int bh = blockIdx.z, k0 = blockIdx.x * 128, q0 = blockIdx.y * 128;
    run_gemm<128>(g_Qv + ((size_t)bh * SS + q0) * DHH, DHH,
                  g_Ph + ((size_t)bh * SS + k0) * DHH, DHH, DHH, sm);
    float* smf = (float*)sm;
    const int tid = threadIdx.x, wid = tid >> 5, lid = tid & 31;
    float* dst = g_S1 + ((size_t)bh * SS + q0) * SS + k0;
#pragma unroll
    for (int it = 0; it < 16; ++it) {
        int r = wid * 16 + it;
        float4 v = *(float4*)(smf + r * 132 + lid * 4);
        *(float4*)(dst + (size_t)r * SS + lid * 4) = v;
    }
}

// ---------------- stage 2b: content + rel_shift + scale ----------------
__global__ __launch_bounds__(256) void k_content() {
    extern __shared__ char sm[];
    const int bh = blockIdx.z, k0 = blockIdx.x * 128, q0 = blockIdx.y * 128;
    run_gemm<128>(g_Qu + ((size_t)bh * SS + q0) * DHH, DHH,
                  g_Kh + ((size_t)bh * SS + k0) * DHH, DHH, DHH, sm);
    float* smf = (float*)sm;
    const int tid = threadIdx.x, wid = tid >> 5, lid = tid & 31;
    const float scale = 0.03125f;
    const float* S1b = g_S1 + (size_t)bh * SS * SS;
#pragma unroll
    for (int it = 0; it < 16; ++it) {
        int r = wid * 16 + it;
        int q = q0 + r;
        const float* s1q  = S1b + (size_t)q * SS;
        const float* s1q1 = S1b + (size_t)(q + 1) * SS;
        float o[4];
#pragma unroll
        for (int j = 0; j < 4; ++j) {
            int k = k0 + lid * 4 + j;
            float pv;
            if (k <= q)          pv = s1q[SS - 1 - q + k];
            else if (k == q + 1) pv = 0.0f;
            else                 pv = s1q1[k - q - 2];
            o[j] = (smf[r * 132 + lid * 4 + j] + pv) * scale;
        }
        *(float4*)(g_S2 + ((size_t)bh * SS + q) * SS + k0 + lid * 4) =
            make_float4(o[0], o[1], o[2], o[3]);
    }
}

// ---------------- stage 3: softmax (in place on g_S2) ----------------
__global__ __launch_bounds__(256) void softmax_kernel() {
    const size_t row = blockIdx.x;
    float* p = g_S2 + row * SS;
    const int t = threadIdx.x;
    float v[8];
    float m = -1e30f;
#pragma unroll
    for (int i = 0; i < 8; i++) { v[i] = p[t + i * 256]; m = fmaxf(m, v[i]); }
    __shared__ float red[256];
    red[t] = m; __syncthreads();
    for (int s = 128; s > 0; s >>= 1) {
        if (t < s) red[t] = fmaxf(red[t], red[t + s]);
        __syncthreads();
    }
    m = red[0]; __syncthreads();
    float sum = 0.0f;
#pragma unroll
    for (int i = 0; i < 8; i++) { v[i] = __expf(v[i] - m); sum += v[i]; }
    red[t] = sum; __syncthreads();
    for (int s = 128; s > 0; s >>= 1) {
        if (t < s) red[t] += red[t + s];
        __syncthreads();
    }
    float inv = 1.0f / red[0];
#pragma unroll
    for (int i = 0; i < 8; i++) p[t + i * 256] = v[i] * inv;
}

// ---------------- stage 4: attn @ V ----------------
__global__ __launch_bounds__(256) void k_attnv() {
    extern __shared__ char sm[];
    const int bh = blockIdx.y, q0 = blockIdx.x * 128;
    const int b = bh >> 4, h = bh & (HH - 1);
    run_gemm<64>(g_S2 + ((size_t)bh * SS + q0) * SS, SS,
                 g_VhT + (size_t)bh * DHH * SS, SS, SS, sm);
    float* smf = (float*)sm;
    const int tid = threadIdx.x, wid = tid >> 5, lid = tid & 31;
    const int col4 = (lid & 15) * 4;
#pragma unroll
    for (int it = 0; it < 8; ++it) {
        int r = wid * 16 + (lid >> 4) + it * 2;
        float4 v = *(float4*)(smf + r * 68 + col4);
        int q = q0 + r;
        *(float4*)(g_O + ((size_t)b * SS + q) * DD + h * 64 + col4) = v;
    }
}

// ---------------- stage 5: output projection ----------------
__global__ __launch_bounds__(256) void k_outproj(
    const float* __restrict__ Wo, const float* __restrict__ bo, float* __restrict__ out)
{
    extern __shared__ char sm[];
    const int n0 = blockIdx.x * 128, m0 = blockIdx.y * 128;
    run_gemm<128>(g_O + (size_t)m0 * DD, DD, Wo + (size_t)n0 * DD, DD, DD, sm);
    float* smf = (float*)sm;
    const int tid = threadIdx.x, wid = tid >> 5, lid = tid & 31;
    float4 bb = *(const float4*)(bo + n0 + lid * 4);
#pragma unroll
    for (int it = 0; it < 16; ++it) {
        int r = wid * 16 + it;
        float4 v = *(float4*)(smf + r * 132 + lid * 4);
        v.x += bb.x; v.y += bb.y; v.z += bb.z; v.w += bb.w;
        *(float4*)(out + (size_t)(m0 + r) * DD + n0 + lid * 4) = v;
    }
}

// ---------------- launch ----------------
extern "C" void kernel_launch(void* const* d_in, const int* in_sizes, int n_in,
                              void* d_out, int out_size)
{
    const float* q  = (const float*)d_in[0];
    const float* k  = (const float*)d_in[1];
    const float* v  = (const float*)d_in[2];
    const float* pe = (const float*)d_in[3];
    const float* Wq = (const float*)d_in[4];
    const float* bq = (const float*)d_in[5];
    const float* Wk = (const float*)d_in[6];
    const float* bk = (const float*)d_in[7];
    const float* Wv = (const float*)d_in[8];
    const float* bv = (const float*)d_in[9];
    const float* Wp = (const float*)d_in[10];
    const float* ub = (const float*)d_in[11];
    const float* vb = (const float*)d_in[12];
    const float* Wo = (const float*)d_in[13];
    const float* bo = (const float*)d_in[14];
    float* out = (float*)d_out;

    const int S128 = 67584;   // max(2 x 32KB stages = 65536, 128*132*4 = 67584)
    const int S64  = 49152;   // max(2 x 24KB stages = 49152, 128*68*4 = 34816)
    cudaFuncSetAttribute(k_proj,    cudaFuncAttributeMaxDynamicSharedMemorySize, S128);
    cudaFuncSetAttribute(k_pos,     cudaFuncAttributeMaxDynamicSharedMemorySize, S128);
    cudaFuncSetAttribute(k_content, cudaFuncAttributeMaxDynamicSharedMemorySize, S128);
    cudaFuncSetAttribute(k_outproj, cudaFuncAttributeMaxDynamicSharedMemorySize, S128);
    cudaFuncSetAttribute(k_attnv,   cudaFuncAttributeMaxDynamicSharedMemorySize, S64);

    dim3 gproj(DD / 128, MM / 128);          // 8 x 32
    k_proj<<<gproj, 256, S128>>>(q,  Wq, bq, ub, vb, 0);
    k_proj<<<gproj, 256, S128>>>(k,  Wk, bk, nullptr, nullptr, 1);
    k_proj<<<gproj, 256, S128>>>(v,  Wv, bv, nullptr, nullptr, 2);
    k_proj<<<gproj, 256, S128>>>(pe, Wp, nullptr, nullptr, nullptr, 3);

    k_transpose<<<dim3(SS / 32, DHH / 32, BHH), dim3(32, 8)>>>();

    dim3 gsc(SS / 128, SS / 128, BHH);       // 16 x 16 x 32
    k_pos<<<gsc, 256, S128>>>();
    k_content<<<gsc, 256, S128>>>();

    softmax_kernel<<<BHH * SS, 256>>>();

    k_attnv<<<dim3(SS / 128, BHH), 256, S64>>>();

    k_outproj<<<dim3(DD / 128, MM / 128), 256, S128>>>(Wo, bo, out);
}